// round 4
// baseline (speedup 1.0000x reference)
#include <cuda_runtime.h>
#include <math.h>

#define HEAD   16
#define HDIM   64
#define NROT   32
#define BATCH  8
#define SEQ    4096
#define NROWS  (BATCH * SEQ * HEAD)   // 524288 rows of 64 floats
#define ROWS_PER_BLK 256

// Combined linear map: blended-rotation composition @ r_matrix, columns permuted
// so that col d<32 = original col 2d (x1) and col d>=32 = original col 2(d-32)+1 (x2).
__device__ float g_M[HDIM * HDIM];
// Per-position table: for each s in [0,4096): cos[0..31], sin[0..31]
__device__ float g_tab[SEQ * 64];

// ---------------------------------------------------------------------------
// Setup kernel (unchanged from R3: passed with rel_err 2.2e-7).
// ---------------------------------------------------------------------------
__global__ void setup_kernel(const float* __restrict__ thetas,
                             const float* __restrict__ theta_scale,
                             const float* __restrict__ r_matrix,
                             const float* __restrict__ inv_freq,
                             const int*   __restrict__ pairs) {
    if (blockIdx.x == 0) {
        __shared__ float E[HDIM * HDIM];
        __shared__ float sR[HDIM * HDIM];
        int t = threadIdx.x;  // 256 threads

        #pragma unroll
        for (int i = 0; i < 16; i++) sR[t + 256 * i] = r_matrix[t + 256 * i];

        if (t < HDIM) {
            int r = t;
            float row[HDIM];
            #pragma unroll
            for (int c = 0; c < HDIM; c++) row[c] = (r == c) ? 1.0f : 0.0f;
            float ts = theta_scale[0];
            for (int st = 0; st < NROT; st++) {
                int i = pairs[2 * st + 0];
                int j = pairs[2 * st + 1];
                float th = thetas[st] * ts;
                float c = cosf(th);
                float s = sinf(th);
                float xi = row[i];
                float xj = row[j];
                float gi = xi * c + xj * s;
                float gj = -xi * s + xj * c;
                row[i] = (2.0f * gi + xi - 2.0f * gi * c) * (1.0f / 3.0f);
                row[j] = (2.0f * gj + xj - 2.0f * gi * s) * (1.0f / 3.0f);
            }
            #pragma unroll
            for (int c = 0; c < HDIM; c++) E[r * HDIM + c] = row[c];
        }
        __syncthreads();

        int r  = t >> 2;
        int dl = t & 3;
        #pragma unroll
        for (int k = 0; k < 16; k++) {
            int d = dl + 4 * k;
            int col = (d < 32) ? (2 * d) : (2 * (d - 32) + 1);
            float acc = 0.0f;
            #pragma unroll
            for (int c = 0; c < HDIM; c++)
                acc = fmaf(E[r * HDIM + c], sR[c * HDIM + col], acc);
            g_M[r * HDIM + d] = acc;
        }
    } else {
        int idx = (blockIdx.x - 1) * 256 + threadIdx.x;  // < SEQ*32
        int s = idx >> 5;
        int d = idx & 31;
        float a = (float)s * inv_freq[d];          // same fp32 rounding as reference
        float k = rintf(a * 0.15915494309189535f); // k <= 652, exact
        float rr = fmaf(-k, 6.28125f, a);
        rr = fmaf(-k, 1.9353071795e-3f, rr);
        rr = fmaf(-k, 8.908910206762e-10f, rr);
        g_tab[s * 64 + d]      = cosf(rr);
        g_tab[s * 64 + 32 + d] = sinf(rr);
    }
}

// ---------------------------------------------------------------------------
// Main kernel: out = RoPE_diag( x @ M ).
// 1 thread = 1 row x all 64 cols. M loads are warp-uniform (crossbar broadcast
// = 1 cyc each); A is one scalar/lane/k via an XOR-swizzled (kg ^ (row&7))
// conflict-free LDS.128 per 4 k. acc = 32 packed f32x2.
// ---------------------------------------------------------------------------
extern __shared__ float smem[];

__global__ __launch_bounds__(256, 2)
void rot_main_kernel(const float* __restrict__ x, float* __restrict__ out) {
    float* sM   = smem;                       // 4096 floats (16 KB), sM[k*64+d]
    float* sX   = smem + HDIM * HDIM;         // 256*64 floats (64 KB), swizzled
    float* sTab = sX + ROWS_PER_BLK * HDIM;   // 16*64 floats (4 KB)
    int tid = threadIdx.x;

    {   // M: 4096 floats, 4 float4 per thread
        const float4* src = (const float4*)g_M;
        float4* dst = (float4*)sM;
        #pragma unroll
        for (int i = 0; i < 4; i++) dst[tid + 256 * i] = src[tid + 256 * i];
    }
    {   // tab: 16 positions x 64 floats = 256 float4
        int pos = (blockIdx.x * 16 + (tid >> 4)) & (SEQ - 1);
        ((float4*)sTab)[tid] = ((const float4*)(g_tab + pos * 64))[tid & 15];
    }
    {   // x: swizzled copy. float4 granule f -> row=f>>4, kg=f&15,
        // stored at row*16 + (kg ^ (row&7)). Conflict-balanced STS.128.
        const float4* xs = (const float4*)(x + (size_t)blockIdx.x * ROWS_PER_BLK * HDIM);
        float4* dx = (float4*)sX;
        #pragma unroll
        for (int i = 0; i < 16; i++) {
            int f = tid + i * 256;
            int row = f >> 4, kg = f & 15;
            dx[row * 16 + (kg ^ (row & 7))] = xs[f];
        }
    }
    __syncthreads();

    unsigned xbase, mbase, tbase;
    asm("{ .reg .u64 t; cvta.to.shared.u64 t, %1; cvt.u32.u64 %0, t; }"
        : "=r"(xbase) : "l"((void*)sX));
    asm("{ .reg .u64 t; cvta.to.shared.u64 t, %1; cvt.u32.u64 %0, t; }"
        : "=r"(mbase) : "l"((void*)sM));
    asm("{ .reg .u64 t; cvta.to.shared.u64 t, %1; cvt.u32.u64 %0, t; }"
        : "=r"(tbase) : "l"((void*)sTab));

    unsigned arow = xbase + (unsigned)tid * 256u;   // this lane's row
    unsigned rx = (unsigned)(tid & 7) << 4;         // swizzle XOR (bytes)

    // acc[i] = packed cols (2i, 2i+1)
    unsigned long long acc[32];
    #pragma unroll
    for (int p = 0; p < 32; p++) acc[p] = 0ULL;

    #pragma unroll 1
    for (int kg = 0; kg < 16; kg++) {
        float a0, a1, a2, a3;
        asm volatile("ld.shared.v4.f32 {%0, %1, %2, %3}, [%4];"
                     : "=f"(a0), "=f"(a1), "=f"(a2), "=f"(a3)
                     : "r"(arow + (((unsigned)kg << 4) ^ rx)));
        float af[4] = {a0, a1, a2, a3};
        #pragma unroll
        for (int u = 0; u < 4; u++) {
            unsigned long long ad;
            asm("mov.b64 %0, {%1, %1};" : "=l"(ad) : "f"(af[u]));
            unsigned mrow = mbase + (unsigned)(kg * 4 + u) * 256u;
            #pragma unroll
            for (int c = 0; c < 16; c++) {
                unsigned long long m0, m1;   // warp-uniform address -> broadcast
                asm volatile("ld.shared.v2.u64 {%0, %1}, [%2];"
                             : "=l"(m0), "=l"(m1) : "r"(mrow + (unsigned)c * 16u));
                asm("fma.rn.f32x2 %0, %1, %2, %0;" : "+l"(acc[2 * c])     : "l"(ad), "l"(m0));
                asm("fma.rn.f32x2 %0, %1, %2, %0;" : "+l"(acc[2 * c + 1]) : "l"(ad), "l"(m1));
            }
        }
    }

    // Epilogue: y = acc[0..15] (cols 0..31), z = acc[16..31] (cols 32..63)
    // out_lo = y*cos - z*sin ; out_hi = y*sin + z*cos   (all natural f32x2 pairs)
    unsigned trow = tbase + (unsigned)((tid >> 4) & 15) * 256u;
    float* orow = out + ((size_t)blockIdx.x * ROWS_PER_BLK + tid) * HDIM;
    #pragma unroll
    for (int c = 0; c < 16; c += 2) {
        unsigned long long c2a, c2b, s2a, s2b;
        asm volatile("ld.shared.v2.u64 {%0, %1}, [%2];"
                     : "=l"(c2a), "=l"(c2b) : "r"(trow + (unsigned)c * 8u));
        asm volatile("ld.shared.v2.u64 {%0, %1}, [%2];"
                     : "=l"(s2a), "=l"(s2b) : "r"(trow + 128u + (unsigned)c * 8u));
        unsigned long long ns2a = s2a ^ 0x8000000080000000ULL;
        unsigned long long ns2b = s2b ^ 0x8000000080000000ULL;
        unsigned long long lo0, lo1, hi0, hi1, t0, t1, t2, t3;
        asm("mul.rn.f32x2 %0, %1, %2;" : "=l"(t0) : "l"(acc[c]),      "l"(c2a));
        asm("mul.rn.f32x2 %0, %1, %2;" : "=l"(t1) : "l"(acc[c + 1]),  "l"(c2b));
        asm("fma.rn.f32x2 %0, %1, %2, %3;" : "=l"(lo0) : "l"(acc[16 + c]),     "l"(ns2a), "l"(t0));
        asm("fma.rn.f32x2 %0, %1, %2, %3;" : "=l"(lo1) : "l"(acc[16 + c + 1]), "l"(ns2b), "l"(t1));
        asm("mul.rn.f32x2 %0, %1, %2;" : "=l"(t2) : "l"(acc[c]),      "l"(s2a));
        asm("mul.rn.f32x2 %0, %1, %2;" : "=l"(t3) : "l"(acc[c + 1]),  "l"(s2b));
        asm("fma.rn.f32x2 %0, %1, %2, %3;" : "=l"(hi0) : "l"(acc[16 + c]),     "l"(c2a), "l"(t2));
        asm("fma.rn.f32x2 %0, %1, %2, %3;" : "=l"(hi1) : "l"(acc[16 + c + 1]), "l"(c2b), "l"(t3));
        asm volatile("st.global.v2.u64 [%0], {%1, %2};"
                     :: "l"(orow + 2 * c),      "l"(lo0), "l"(lo1) : "memory");
        asm volatile("st.global.v2.u64 [%0], {%1, %2};"
                     :: "l"(orow + 32 + 2 * c), "l"(hi0), "l"(hi1) : "memory");
    }
}

// ---------------------------------------------------------------------------
extern "C" void kernel_launch(void* const* d_in, const int* in_sizes, int n_in,
                              void* d_out, int out_size) {
    const float* x           = (const float*)d_in[0];
    const float* thetas      = (const float*)d_in[1];
    const float* theta_scale = (const float*)d_in[2];
    const float* r_matrix    = (const float*)d_in[3];
    const float* inv_freq    = (const float*)d_in[4];
    const int*   pairs       = (const int*)d_in[5];
    float* out = (float*)d_out;

    static int smem_set = 0;
    const int smem_bytes = (HDIM * HDIM + ROWS_PER_BLK * HDIM + 16 * HDIM) * 4; // 84 KB
    if (!smem_set) {
        cudaFuncSetAttribute(rot_main_kernel,
                             cudaFuncAttributeMaxDynamicSharedMemorySize, smem_bytes);
        smem_set = 1;
    }

    setup_kernel<<<1 + (SEQ * 32) / 256, 256>>>(thetas, theta_scale, r_matrix,
                                                inv_freq, pairs);
    rot_main_kernel<<<NROWS / ROWS_PER_BLK, 256, smem_bytes>>>(x, out);
}

// round 6
// speedup vs baseline: 2.1152x; 2.1152x over previous
#include <cuda_runtime.h>
#include <cuda_bf16.h>
#include <math.h>
#include <cstdint>

#define HDIM   64
#define NROT   32
#define SEQ    4096
#define NROWS  (8 * 4096 * 16)     // 524288 rows of 64 floats
#define TILES_PER_WARP 4           // 16-row tiles per warp
#define NBLOCKS (NROWS / (8 * 16 * TILES_PER_WARP))   // 1024

// B = M^T split into bf16 hi/lo, packed bf16x2 along k: g_B*[n*32 + k2]
__device__ unsigned g_Bhi[HDIM * 32];
__device__ unsigned g_Blo[HDIM * 32];
// Per-position table: cos[0..31], sin[0..31] per s
__device__ float    g_tab[SEQ * 64];

#define SW128(o) ((unsigned)(o) ^ ((((unsigned)(o)) >> 3) & 0x70u))

// ---------------------------------------------------------------------------
// Setup: block 0 builds M (blend @ r_matrix, RoPE column permutation folded)
// and its transposed bf16 hi/lo split; blocks 1..512 build the sin/cos table
// (fp32 Cody-Waite reduction, proven at rel_err 2.2e-7 in R3).
// ---------------------------------------------------------------------------
__global__ void setup_kernel(const float* __restrict__ thetas,
                             const float* __restrict__ theta_scale,
                             const float* __restrict__ r_matrix,
                             const float* __restrict__ inv_freq,
                             const int*   __restrict__ pairs) {
    if (blockIdx.x == 0) {
        __shared__ float E[HDIM * HDIM];
        __shared__ float sR[HDIM * HDIM];
        int t = threadIdx.x;  // 256 threads

        #pragma unroll
        for (int i = 0; i < 16; i++) sR[t + 256 * i] = r_matrix[t + 256 * i];

        if (t < HDIM) {
            int r = t;
            float row[HDIM];
            #pragma unroll
            for (int c = 0; c < HDIM; c++) row[c] = (r == c) ? 1.0f : 0.0f;
            float ts = theta_scale[0];
            for (int st = 0; st < NROT; st++) {
                int i = pairs[2 * st + 0];
                int j = pairs[2 * st + 1];
                float th = thetas[st] * ts;
                float c = cosf(th);
                float s = sinf(th);
                float xi = row[i];
                float xj = row[j];
                float gi = xi * c + xj * s;
                float gj = -xi * s + xj * c;
                row[i] = (2.0f * gi + xi - 2.0f * gi * c) * (1.0f / 3.0f);
                row[j] = (2.0f * gj + xj - 2.0f * gi * s) * (1.0f / 3.0f);
            }
            #pragma unroll
            for (int c = 0; c < HDIM; c++) E[r * HDIM + c] = row[c];
        }
        __syncthreads();

        int r  = t >> 2;
        int dl = t & 3;
        float accv[16];
        #pragma unroll
        for (int k = 0; k < 16; k++) {
            int d = dl + 4 * k;
            int col = (d < 32) ? (2 * d) : (2 * (d - 32) + 1);
            float acc = 0.0f;
            #pragma unroll
            for (int c = 0; c < HDIM; c++)
                acc = fmaf(E[r * HDIM + c], sR[c * HDIM + col], acc);
            accv[k] = acc;
        }
        __syncthreads();   // all matmul reads of E done
        #pragma unroll
        for (int k = 0; k < 16; k++)
            E[r * HDIM + (dl + 4 * k)] = accv[k];   // E now holds M
        __syncthreads();

        // B = M^T bf16 hi/lo split, packed bf16x2 (low half = even k)
        #pragma unroll
        for (int i = 0; i < 8; i++) {
            int e = t + i * 256;            // e = n*32 + k2
            int n = e >> 5, k2 = e & 31;
            float m0 = E[(2 * k2)     * HDIM + n];
            float m1 = E[(2 * k2 + 1) * HDIM + n];
            __nv_bfloat16 h0 = __float2bfloat16_rn(m0);
            __nv_bfloat16 h1 = __float2bfloat16_rn(m1);
            float r0 = m0 - __bfloat162float(h0);
            float r1 = m1 - __bfloat162float(h1);
            __nv_bfloat16 l0 = __float2bfloat16_rn(r0);
            __nv_bfloat16 l1 = __float2bfloat16_rn(r1);
            g_Bhi[e] = (unsigned)__bfloat16_as_ushort(h0) |
                       ((unsigned)__bfloat16_as_ushort(h1) << 16);
            g_Blo[e] = (unsigned)__bfloat16_as_ushort(l0) |
                       ((unsigned)__bfloat16_as_ushort(l1) << 16);
        }
    } else {
        int idx = (blockIdx.x - 1) * 256 + threadIdx.x;  // < SEQ*32
        int s = idx >> 5;
        int d = idx & 31;
        float a = (float)s * inv_freq[d];
        float k = rintf(a * 0.15915494309189535f);
        float rr = fmaf(-k, 6.28125f, a);
        rr = fmaf(-k, 1.9353071795e-3f, rr);
        rr = fmaf(-k, 8.908910206762e-10f, rr);
        g_tab[s * 64 + d]      = cosf(rr);
        g_tab[s * 64 + 32 + d] = sinf(rr);
    }
}

// ---------------------------------------------------------------------------
// helpers
// ---------------------------------------------------------------------------
__device__ __forceinline__ uint32_t smem_u32(const void* p) {
    uint32_t a;
    asm("{ .reg .u64 t; cvta.to.shared.u64 t, %1; cvt.u32.u64 %0, t; }"
        : "=r"(a) : "l"(p));
    return a;
}
__device__ __forceinline__ void ldm_x4(uint32_t* r, uint32_t addr) {
    asm volatile("ldmatrix.sync.aligned.m8n8.x4.shared.b16 {%0,%1,%2,%3}, [%4];"
                 : "=r"(r[0]), "=r"(r[1]), "=r"(r[2]), "=r"(r[3]) : "r"(addr));
}
__device__ __forceinline__ void mma16816(float* c, const uint32_t* a,
                                         uint32_t b0, uint32_t b1) {
    asm volatile(
        "mma.sync.aligned.m16n8k16.row.col.f32.bf16.bf16.f32 "
        "{%0,%1,%2,%3}, {%4,%5,%6,%7}, {%8,%9}, {%0,%1,%2,%3};"
        : "+f"(c[0]), "+f"(c[1]), "+f"(c[2]), "+f"(c[3])
        : "r"(a[0]), "r"(a[1]), "r"(a[2]), "r"(a[3]), "r"(b0), "r"(b1));
}

// SMEM layout (dynamic): Bh [0,8K), Bl [8K,16K), per-warp A: hi 2K + lo 2K
#define OFF_BH 0
#define OFF_BL 8192
#define OFF_A  16384
#define SMEM_TOTAL (16384 + 8 * 4096)   // 49152 = default dyn-smem limit

// ---------------------------------------------------------------------------
// Main kernel: out = RoPE_diag( x @ M ) via bf16 mma.sync with hi/lo split.
// Warp tile = 16 rows x 64 cols (one RoPE position). K=64 as 4 chunks of 16.
// ---------------------------------------------------------------------------
__global__ __launch_bounds__(256, 3)
void rot_mma_kernel(const float* __restrict__ x, float* __restrict__ out) {
    extern __shared__ __align__(1024) char smem[];
    uint32_t sb = smem_u32(smem);
    int tid = threadIdx.x, w = tid >> 5, l = tid & 31;

    // stage B hi/lo swizzled ([n][k] bf16, 128B rows, SW128)
    #pragma unroll
    for (int i = 0; i < 8; i++) {
        int e = tid + i * 256;               // e = n*32 + k2
        int n = e >> 5, k2 = e & 31;
        unsigned sw = SW128(n * 128 + k2 * 4);
        unsigned bh = g_Bhi[e], bl = g_Blo[e];
        asm volatile("st.shared.b32 [%0], %1;" :: "r"(sb + OFF_BH + sw), "r"(bh) : "memory");
        asm volatile("st.shared.b32 [%0], %1;" :: "r"(sb + OFF_BL + sw), "r"(bl) : "memory");
    }
    __syncthreads();

    uint32_t aHi = sb + OFF_A + (unsigned)w * 4096u;
    uint32_t aLo = aHi + 2048u;

    // precomputed ldmatrix source addresses (lane-dependent parts)
    unsigned aAddrBase = SW128(((unsigned)(l & 15)) * 128u + ((unsigned)(l >> 4)) * 16u);
    // note: SW128 is XOR with (row&7)<<4; adding kc*32 later changes chunk bits,
    // so recompute per kc instead of adding. Keep raw components:
    unsigned aRow = (unsigned)(l & 15);
    unsigned aKhalf = (unsigned)(l >> 4) * 16u;
    unsigned bRow0 = (unsigned)(l & 7) + ((unsigned)((l >> 4) & 1)) * 8u;
    unsigned bKoff = ((unsigned)((l >> 3) & 1)) * 16u;
    (void)aAddrBase;

    size_t warpRow0 = ((size_t)blockIdx.x * 8 + w) * (16 * TILES_PER_WARP);

    for (int it = 0; it < TILES_PER_WARP; it++) {
        size_t rb = warpRow0 + (size_t)it * 16;
        const float4* xs = (const float4*)(x + rb * HDIM);

        __syncwarp();
        // load 16x64 f32 tile (coalesced), split to bf16 hi/lo, swizzled STS
        #pragma unroll
        for (int i = 0; i < 8; i++) {
            int f = l + 32 * i;
            float4 v = xs[f];                 // LDG.128
            unsigned h01, h23, l01, l23;
            asm("cvt.rn.bf16x2.f32 %0, %1, %2;" : "=r"(h01) : "f"(v.y), "f"(v.x));
            asm("cvt.rn.bf16x2.f32 %0, %1, %2;" : "=r"(h23) : "f"(v.w), "f"(v.z));
            float rx = v.x - __uint_as_float(h01 << 16);
            float ry = v.y - __uint_as_float(h01 & 0xFFFF0000u);
            float rz = v.z - __uint_as_float(h23 << 16);
            float rw = v.w - __uint_as_float(h23 & 0xFFFF0000u);
            asm("cvt.rn.bf16x2.f32 %0, %1, %2;" : "=r"(l01) : "f"(ry), "f"(rx));
            asm("cvt.rn.bf16x2.f32 %0, %1, %2;" : "=r"(l23) : "f"(rw), "f"(rz));
            int r = f >> 4, kq = f & 15;
            unsigned sw = SW128((unsigned)(r * 128 + kq * 8));
            asm volatile("st.shared.v2.b32 [%0], {%1, %2};"
                         :: "r"(aHi + sw), "r"(h01), "r"(h23) : "memory");
            asm volatile("st.shared.v2.b32 [%0], {%1, %2};"
                         :: "r"(aLo + sw), "r"(l01), "r"(l23) : "memory");
        }
        __syncwarp();

        float acc[32];
        #pragma unroll
        for (int p = 0; p < 32; p++) acc[p] = 0.0f;

        #pragma unroll
        for (int kc = 0; kc < 4; kc++) {
            uint32_t ah[4], al[4];
            unsigned aad = SW128(aRow * 128u + (unsigned)kc * 32u + aKhalf);
            ldm_x4(ah, aHi + aad);
            ldm_x4(al, aLo + aad);
            #pragma unroll
            for (int np = 0; np < 4; np++) {
                unsigned bad = SW128((16u * np + bRow0) * 128u + (unsigned)kc * 32u + bKoff);
                uint32_t bh[4];
                ldm_x4(bh, sb + OFF_BH + bad);
                mma16816(acc + (2 * np) * 4,     ah, bh[0], bh[1]);
                mma16816(acc + (2 * np + 1) * 4, ah, bh[2], bh[3]);
                mma16816(acc + (2 * np) * 4,     al, bh[0], bh[1]);
                mma16816(acc + (2 * np + 1) * 4, al, bh[2], bh[3]);
                uint32_t bl[4];
                ldm_x4(bl, sb + OFF_BL + bad);
                mma16816(acc + (2 * np) * 4,     ah, bl[0], bl[1]);
                mma16816(acc + (2 * np + 1) * 4, ah, bl[2], bl[3]);
            }
        }

        // RoPE epilogue. Tile rows share one position s (16 heads per (b,s)).
        // D frag: lane l -> rows g=l>>2 and g+8, cols 2(l&3), 2(l&3)+1 per n-tile.
        // n-tile t in 0..3 = output cols 8t+cb (lo half, "y");
        // n-tile t+4      = output cols 32+8t+cb ("z").
        int pos = (int)((rb >> 4) & (SEQ - 1));
        const float* tb = g_tab + pos * 64;
        int g  = l >> 2;
        int cb = 2 * (l & 3);
        float* o0 = out + (rb + g) * HDIM;
        float* o1 = out + (rb + g + 8) * HDIM;
        #pragma unroll
        for (int t = 0; t < 4; t++) {
            int c = 8 * t + cb;
            float2 cc = *(const float2*)(tb + c);
            float2 ss = *(const float2*)(tb + 32 + c);
            const float* y = acc + t * 4;
            const float* z = acc + (t + 4) * 4;
            float2 lo0, hi0, lo1, hi1;
            lo0.x = y[0] * cc.x - z[0] * ss.x;
            lo0.y = y[1] * cc.y - z[1] * ss.y;
            hi0.x = y[0] * ss.x + z[0] * cc.x;
            hi0.y = y[1] * ss.y + z[1] * cc.y;
            lo1.x = y[2] * cc.x - z[2] * ss.x;
            lo1.y = y[3] * cc.y - z[3] * ss.y;
            hi1.x = y[2] * ss.x + z[2] * cc.x;
            hi1.y = y[3] * ss.y + z[3] * cc.y;
            *(float2*)(o0 + c)      = lo0;
            *(float2*)(o0 + 32 + c) = hi0;
            *(float2*)(o1 + c)      = lo1;
            *(float2*)(o1 + 32 + c) = hi1;
        }
    }
}

// ---------------------------------------------------------------------------
extern "C" void kernel_launch(void* const* d_in, const int* in_sizes, int n_in,
                              void* d_out, int out_size) {
    const float* x           = (const float*)d_in[0];
    const float* thetas      = (const float*)d_in[1];
    const float* theta_scale = (const float*)d_in[2];
    const float* r_matrix    = (const float*)d_in[3];
    const float* inv_freq    = (const float*)d_in[4];
    const int*   pairs       = (const int*)d_in[5];
    float* out = (float*)d_out;

    setup_kernel<<<1 + (SEQ * 32) / 256, 256>>>(thetas, theta_scale, r_matrix,
                                                inv_freq, pairs);
    rot_mma_kernel<<<NBLOCKS, 256, SMEM_TOTAL>>>(x, out);
}

// round 7
// speedup vs baseline: 2.5044x; 1.1840x over previous
#include <cuda_runtime.h>
#include <cuda_bf16.h>
#include <math.h>
#include <cstdint>

#define HDIM   64
#define NROT   32
#define SEQ    4096
#define NROWS  (8 * 4096 * 16)     // 524288 rows of 64 floats
#define ROWS_PER_WARP 64           // 2 iterations x 32 rows
#define NBLOCKS (NROWS / (8 * ROWS_PER_WARP))   // 1024

// B = M^T split into bf16 hi/lo, packed bf16x2 along k: g_B*[n*32 + k2]
__device__ unsigned g_Bhi[HDIM * 32];
__device__ unsigned g_Blo[HDIM * 32];
// Per-position table: cos[0..31], sin[0..31] per s
__device__ float    g_tab[SEQ * 64];

#define SW128(o) ((unsigned)(o) ^ ((((unsigned)(o)) >> 3) & 0x70u))

// ---------------------------------------------------------------------------
// Setup: block 0 builds M (blend @ r_matrix, RoPE column permutation folded)
// and its transposed bf16 hi/lo split; blocks 1..512 build the sin/cos table
// (fp32 Cody-Waite reduction, proven at rel_err ~2e-7 in R3).
// ---------------------------------------------------------------------------
__global__ void setup_kernel(const float* __restrict__ thetas,
                             const float* __restrict__ theta_scale,
                             const float* __restrict__ r_matrix,
                             const float* __restrict__ inv_freq,
                             const int*   __restrict__ pairs) {
    if (blockIdx.x == 0) {
        __shared__ float E[HDIM * HDIM];
        __shared__ float sR[HDIM * HDIM];
        int t = threadIdx.x;  // 256 threads

        #pragma unroll
        for (int i = 0; i < 16; i++) sR[t + 256 * i] = r_matrix[t + 256 * i];

        if (t < HDIM) {
            int r = t;
            float row[HDIM];
            #pragma unroll
            for (int c = 0; c < HDIM; c++) row[c] = (r == c) ? 1.0f : 0.0f;
            float ts = theta_scale[0];
            for (int st = 0; st < NROT; st++) {
                int i = pairs[2 * st + 0];
                int j = pairs[2 * st + 1];
                float th = thetas[st] * ts;
                float c = cosf(th);
                float s = sinf(th);
                float xi = row[i];
                float xj = row[j];
                float gi = xi * c + xj * s;
                float gj = -xi * s + xj * c;
                row[i] = (2.0f * gi + xi - 2.0f * gi * c) * (1.0f / 3.0f);
                row[j] = (2.0f * gj + xj - 2.0f * gi * s) * (1.0f / 3.0f);
            }
            #pragma unroll
            for (int c = 0; c < HDIM; c++) E[r * HDIM + c] = row[c];
        }
        __syncthreads();

        int r  = t >> 2;
        int dl = t & 3;
        float accv[16];
        #pragma unroll
        for (int k = 0; k < 16; k++) {
            int d = dl + 4 * k;
            int col = (d < 32) ? (2 * d) : (2 * (d - 32) + 1);
            float acc = 0.0f;
            #pragma unroll
            for (int c = 0; c < HDIM; c++)
                acc = fmaf(E[r * HDIM + c], sR[c * HDIM + col], acc);
            accv[k] = acc;
        }
        __syncthreads();   // all matmul reads of E done
        #pragma unroll
        for (int k = 0; k < 16; k++)
            E[r * HDIM + (dl + 4 * k)] = accv[k];   // E now holds M
        __syncthreads();

        // B = M^T bf16 hi/lo split, packed bf16x2 (low half = even k)
        #pragma unroll
        for (int i = 0; i < 8; i++) {
            int e = t + i * 256;            // e = n*32 + k2
            int n = e >> 5, k2 = e & 31;
            float m0 = E[(2 * k2)     * HDIM + n];
            float m1 = E[(2 * k2 + 1) * HDIM + n];
            __nv_bfloat16 h0 = __float2bfloat16_rn(m0);
            __nv_bfloat16 h1 = __float2bfloat16_rn(m1);
            float r0 = m0 - __bfloat162float(h0);
            float r1 = m1 - __bfloat162float(h1);
            __nv_bfloat16 l0 = __float2bfloat16_rn(r0);
            __nv_bfloat16 l1 = __float2bfloat16_rn(r1);
            g_Bhi[e] = (unsigned)__bfloat16_as_ushort(h0) |
                       ((unsigned)__bfloat16_as_ushort(h1) << 16);
            g_Blo[e] = (unsigned)__bfloat16_as_ushort(l0) |
                       ((unsigned)__bfloat16_as_ushort(l1) << 16);
        }
    } else {
        int idx = (blockIdx.x - 1) * 256 + threadIdx.x;  // < SEQ*32
        int s = idx >> 5;
        int d = idx & 31;
        float a = (float)s * inv_freq[d];
        float k = rintf(a * 0.15915494309189535f);
        float rr = fmaf(-k, 6.28125f, a);
        rr = fmaf(-k, 1.9353071795e-3f, rr);
        rr = fmaf(-k, 8.908910206762e-10f, rr);
        g_tab[s * 64 + d]      = cosf(rr);
        g_tab[s * 64 + 32 + d] = sinf(rr);
    }
}

// ---------------------------------------------------------------------------
// helpers
// ---------------------------------------------------------------------------
__device__ __forceinline__ uint32_t smem_u32(const void* p) {
    uint32_t a;
    asm("{ .reg .u64 t; cvta.to.shared.u64 t, %1; cvt.u32.u64 %0, t; }"
        : "=r"(a) : "l"(p));
    return a;
}
__device__ __forceinline__ void ldm_x4(uint32_t* r, uint32_t addr) {
    asm volatile("ldmatrix.sync.aligned.m8n8.x4.shared.b16 {%0,%1,%2,%3}, [%4];"
                 : "=r"(r[0]), "=r"(r[1]), "=r"(r[2]), "=r"(r[3]) : "r"(addr));
}
__device__ __forceinline__ void mma16816(float* c, const uint32_t* a,
                                         uint32_t b0, uint32_t b1) {
    asm volatile(
        "mma.sync.aligned.m16n8k16.row.col.f32.bf16.bf16.f32 "
        "{%0,%1,%2,%3}, {%4,%5,%6,%7}, {%8,%9}, {%0,%1,%2,%3};"
        : "+f"(c[0]), "+f"(c[1]), "+f"(c[2]), "+f"(c[3])
        : "r"(a[0]), "r"(a[1]), "r"(a[2]), "r"(a[3]), "r"(b0), "r"(b1));
}
// split float2 into packed bf16x2 hi + packed bf16x2 residual
__device__ __forceinline__ void split2(float2 v, uint32_t& h, uint32_t& lo) {
    asm("cvt.rn.bf16x2.f32 %0, %1, %2;" : "=r"(h) : "f"(v.y), "f"(v.x));
    float rx = v.x - __uint_as_float(h << 16);
    float ry = v.y - __uint_as_float(h & 0xFFFF0000u);
    asm("cvt.rn.bf16x2.f32 %0, %1, %2;" : "=r"(lo) : "f"(ry), "f"(rx));
}

// SMEM: Bh [0,8K), Bl [8K,16K)
#define OFF_BH 0
#define OFF_BL 8192
#define SMEM_TOTAL 16384

// ---------------------------------------------------------------------------
// Main kernel: out = RoPE_diag( x @ M ) via bf16 mma.sync with hi/lo split.
// Warp iteration = 32 rows = 2 m16 strips sharing every B fragment load.
// A fragments are loaded straight from global in mma layout (no smem trip):
// lane l (g=l>>2, c=l&3) reads float2 at rows {g, g+8}, k {16kc+2c, 16kc+8+2c}
// -> 8 rows x 32B contiguous per LDG.64, fully coalesced.
// ---------------------------------------------------------------------------
__global__ __launch_bounds__(256, 2)
void rot_mma_kernel(const float* __restrict__ x, float* __restrict__ out) {
    extern __shared__ __align__(1024) char smem[];
    uint32_t sb = smem_u32(smem);
    int tid = threadIdx.x, w = tid >> 5, l = tid & 31;

    // stage B hi/lo swizzled ([n][k] bf16, 128B rows, SW128)
    #pragma unroll
    for (int i = 0; i < 8; i++) {
        int e = tid + i * 256;               // e = n*32 + k2
        int n = e >> 5, k2 = e & 31;
        unsigned sw = SW128(n * 128 + k2 * 4);
        unsigned bh = g_Bhi[e], bl = g_Blo[e];
        asm volatile("st.shared.b32 [%0], %1;" :: "r"(sb + OFF_BH + sw), "r"(bh) : "memory");
        asm volatile("st.shared.b32 [%0], %1;" :: "r"(sb + OFF_BL + sw), "r"(bl) : "memory");
    }
    __syncthreads();

    int g = l >> 2, c = l & 3;
    unsigned bRow0 = (unsigned)(l & 7) + ((unsigned)((l >> 4) & 1)) * 8u;
    unsigned bKoff = ((unsigned)((l >> 3) & 1)) * 16u;
    int cb = 2 * c;

    size_t warpRow0 = ((size_t)blockIdx.x * 8 + w) * ROWS_PER_WARP;

    #pragma unroll 1
    for (int it = 0; it < ROWS_PER_WARP / 32; it++) {
        size_t rb0 = warpRow0 + (size_t)it * 32;       // strip0; strip1 = +16
        const float* xb = x + rb0 * HDIM;

        float acc0[32], acc1[32];
        #pragma unroll
        for (int p = 0; p < 32; p++) { acc0[p] = 0.0f; acc1[p] = 0.0f; }

        #pragma unroll
        for (int kc = 0; kc < 4; kc++) {
            // A fragments for both strips, direct from global
            uint32_t ah0[4], al0[4], ah1[4], al1[4];
            {
                const float* p0 = xb + g * HDIM + kc * 16 + cb;
                float2 v0 = *(const float2*)(p0);
                float2 v1 = *(const float2*)(p0 + 8 * HDIM);
                float2 v2 = *(const float2*)(p0 + 8);
                float2 v3 = *(const float2*)(p0 + 8 * HDIM + 8);
                split2(v0, ah0[0], al0[0]);
                split2(v1, ah0[1], al0[1]);
                split2(v2, ah0[2], al0[2]);
                split2(v3, ah0[3], al0[3]);
                const float* p1 = p0 + 16 * HDIM;
                float2 u0 = *(const float2*)(p1);
                float2 u1 = *(const float2*)(p1 + 8 * HDIM);
                float2 u2 = *(const float2*)(p1 + 8);
                float2 u3 = *(const float2*)(p1 + 8 * HDIM + 8);
                split2(u0, ah1[0], al1[0]);
                split2(u1, ah1[1], al1[1]);
                split2(u2, ah1[2], al1[2]);
                split2(u3, ah1[3], al1[3]);
            }
            #pragma unroll
            for (int np = 0; np < 4; np++) {
                unsigned bad = SW128((16u * np + bRow0) * 128u + (unsigned)kc * 32u + bKoff);
                uint32_t bh[4];
                ldm_x4(bh, sb + OFF_BH + bad);
                mma16816(acc0 + (2 * np) * 4,     ah0, bh[0], bh[1]);
                mma16816(acc0 + (2 * np + 1) * 4, ah0, bh[2], bh[3]);
                mma16816(acc1 + (2 * np) * 4,     ah1, bh[0], bh[1]);
                mma16816(acc1 + (2 * np + 1) * 4, ah1, bh[2], bh[3]);
                mma16816(acc0 + (2 * np) * 4,     al0, bh[0], bh[1]);
                mma16816(acc0 + (2 * np + 1) * 4, al0, bh[2], bh[3]);
                mma16816(acc1 + (2 * np) * 4,     al1, bh[0], bh[1]);
                mma16816(acc1 + (2 * np + 1) * 4, al1, bh[2], bh[3]);
                uint32_t bl[4];
                ldm_x4(bl, sb + OFF_BL + bad);
                mma16816(acc0 + (2 * np) * 4,     ah0, bl[0], bl[1]);
                mma16816(acc0 + (2 * np + 1) * 4, ah0, bl[2], bl[3]);
                mma16816(acc1 + (2 * np) * 4,     ah1, bl[0], bl[1]);
                mma16816(acc1 + (2 * np + 1) * 4, ah1, bl[2], bl[3]);
            }
        }

        // RoPE epilogue per strip. D frag: lane -> rows {g, g+8}, cols
        // {8t+cb, 8t+cb+1}; n-tiles t (y, cols<32) pair with t+4 (z, cols+32).
        #pragma unroll
        for (int s = 0; s < 2; s++) {
            const float* acc = s ? acc1 : acc0;
            size_t rb = rb0 + (size_t)s * 16;
            int pos = (int)((rb >> 4) & (SEQ - 1));
            const float* tb = g_tab + pos * 64;
            float* o0 = out + (rb + g) * HDIM;
            float* o1 = out + (rb + g + 8) * HDIM;
            #pragma unroll
            for (int t = 0; t < 4; t++) {
                int cc2 = 8 * t + cb;
                float2 cc = __ldg((const float2*)(tb + cc2));
                float2 ss = __ldg((const float2*)(tb + 32 + cc2));
                const float* y = acc + t * 4;
                const float* z = acc + (t + 4) * 4;
                float2 lo0, hi0, lo1, hi1;
                lo0.x = y[0] * cc.x - z[0] * ss.x;
                lo0.y = y[1] * cc.y - z[1] * ss.y;
                hi0.x = y[0] * ss.x + z[0] * cc.x;
                hi0.y = y[1] * ss.y + z[1] * cc.y;
                lo1.x = y[2] * cc.x - z[2] * ss.x;
                lo1.y = y[3] * cc.y - z[3] * ss.y;
                hi1.x = y[2] * ss.x + z[2] * cc.x;
                hi1.y = y[3] * ss.y + z[3] * cc.y;
                *(float2*)(o0 + cc2)      = lo0;
                *(float2*)(o0 + 32 + cc2) = hi0;
                *(float2*)(o1 + cc2)      = lo1;
                *(float2*)(o1 + 32 + cc2) = hi1;
            }
        }
    }
}

// ---------------------------------------------------------------------------
extern "C" void kernel_launch(void* const* d_in, const int* in_sizes, int n_in,
                              void* d_out, int out_size) {
    const float* x           = (const float*)d_in[0];
    const float* thetas      = (const float*)d_in[1];
    const float* theta_scale = (const float*)d_in[2];
    const float* r_matrix    = (const float*)d_in[3];
    const float* inv_freq    = (const float*)d_in[4];
    const int*   pairs       = (const int*)d_in[5];
    float* out = (float*)d_out;

    setup_kernel<<<1 + (SEQ * 32) / 256, 256>>>(thetas, theta_scale, r_matrix,
                                                inv_freq, pairs);
    rot_mma_kernel<<<NBLOCKS, 256, SMEM_TOTAL>>>(x, out);
}

// round 8
// speedup vs baseline: 2.7582x; 1.1013x over previous
#include <cuda_runtime.h>
#include <cuda_bf16.h>
#include <math.h>
#include <cstdint>

#define HDIM   64
#define NROT   32
#define SEQ    4096
#define NROWS  (8 * 4096 * 16)     // 524288 rows of 64 floats
#define NBLOCKS (NROWS / (8 * 32))   // 2048: 8 warps x 32 rows per block

// B = M^T split into bf16 hi/lo, packed bf16x2, k stored in FRAG order:
// frag pair fp within each 8-pair chunk holds phys pair 2*(fp&3)+(fp>>2).
__device__ unsigned g_Bhi[HDIM * 32];
__device__ unsigned g_Blo[HDIM * 32];

#define SW128(o) ((unsigned)(o) ^ ((((unsigned)(o)) >> 3) & 0x70u))

// ---------------------------------------------------------------------------
// Setup: single block. Builds M (blend @ r_matrix with RoPE column permutation
// folded in), then the transposed bf16 hi/lo split with frag-order k.
// ---------------------------------------------------------------------------
__global__ void setup_kernel(const float* __restrict__ thetas,
                             const float* __restrict__ theta_scale,
                             const float* __restrict__ r_matrix,
                             const int*   __restrict__ pairs) {
    __shared__ float E[HDIM * HDIM];
    __shared__ float sR[HDIM * HDIM];
    int t = threadIdx.x;  // 256 threads

    #pragma unroll
    for (int i = 0; i < 16; i++) sR[t + 256 * i] = r_matrix[t + 256 * i];

    if (t < HDIM) {
        int r = t;
        float row[HDIM];
        #pragma unroll
        for (int c = 0; c < HDIM; c++) row[c] = (r == c) ? 1.0f : 0.0f;
        float ts = theta_scale[0];
        for (int st = 0; st < NROT; st++) {
            int i = pairs[2 * st + 0];
            int j = pairs[2 * st + 1];
            float th = thetas[st] * ts;
            float c = cosf(th);
            float s = sinf(th);
            float xi = row[i];
            float xj = row[j];
            float gi = xi * c + xj * s;
            float gj = -xi * s + xj * c;
            row[i] = (2.0f * gi + xi - 2.0f * gi * c) * (1.0f / 3.0f);
            row[j] = (2.0f * gj + xj - 2.0f * gi * s) * (1.0f / 3.0f);
        }
        #pragma unroll
        for (int c = 0; c < HDIM; c++) E[r * HDIM + c] = row[c];
    }
    __syncthreads();

    int r  = t >> 2;
    int dl = t & 3;
    float accv[16];
    #pragma unroll
    for (int k = 0; k < 16; k++) {
        int d = dl + 4 * k;
        int col = (d < 32) ? (2 * d) : (2 * (d - 32) + 1);
        float acc = 0.0f;
        #pragma unroll
        for (int c = 0; c < HDIM; c++)
            acc = fmaf(E[r * HDIM + c], sR[c * HDIM + col], acc);
        accv[k] = acc;
    }
    __syncthreads();   // all matmul reads of E done
    #pragma unroll
    for (int k = 0; k < 16; k++)
        E[r * HDIM + (dl + 4 * k)] = accv[k];   // E now holds M
    __syncthreads();

    // B = M^T bf16 hi/lo split; k pairs permuted to frag order so the main
    // kernel can load A as contiguous float4 with zero repacking.
    #pragma unroll
    for (int i = 0; i < 8; i++) {
        int e = t + i * 256;            // e = n*32 + fk2 (frag pair index)
        int n = e >> 5, fk2 = e & 31;
        int fp = fk2 & 7, chunk = fk2 >> 3;
        int p2 = chunk * 8 + 2 * (fp & 3) + (fp >> 2);   // phys pair
        float m0 = E[(2 * p2)     * HDIM + n];
        float m1 = E[(2 * p2 + 1) * HDIM + n];
        __nv_bfloat16 h0 = __float2bfloat16_rn(m0);
        __nv_bfloat16 h1 = __float2bfloat16_rn(m1);
        float r0 = m0 - __bfloat162float(h0);
        float r1 = m1 - __bfloat162float(h1);
        __nv_bfloat16 l0 = __float2bfloat16_rn(r0);
        __nv_bfloat16 l1 = __float2bfloat16_rn(r1);
        g_Bhi[e] = (unsigned)__bfloat16_as_ushort(h0) |
                   ((unsigned)__bfloat16_as_ushort(h1) << 16);
        g_Blo[e] = (unsigned)__bfloat16_as_ushort(l0) |
                   ((unsigned)__bfloat16_as_ushort(l1) << 16);
    }
}

// ---------------------------------------------------------------------------
// helpers
// ---------------------------------------------------------------------------
__device__ __forceinline__ uint32_t smem_u32(const void* p) {
    uint32_t a;
    asm("{ .reg .u64 t; cvta.to.shared.u64 t, %1; cvt.u32.u64 %0, t; }"
        : "=r"(a) : "l"(p));
    return a;
}
__device__ __forceinline__ void ldm_x4(uint32_t* r, uint32_t addr) {
    asm volatile("ldmatrix.sync.aligned.m8n8.x4.shared.b16 {%0,%1,%2,%3}, [%4];"
                 : "=r"(r[0]), "=r"(r[1]), "=r"(r[2]), "=r"(r[3]) : "r"(addr));
}
__device__ __forceinline__ void mma16816(float* c, const uint32_t* a,
                                         uint32_t b0, uint32_t b1) {
    asm volatile(
        "mma.sync.aligned.m16n8k16.row.col.f32.bf16.bf16.f32 "
        "{%0,%1,%2,%3}, {%4,%5,%6,%7}, {%8,%9}, {%0,%1,%2,%3};"
        : "+f"(c[0]), "+f"(c[1]), "+f"(c[2]), "+f"(c[3])
        : "r"(a[0]), "r"(a[1]), "r"(a[2]), "r"(a[3]), "r"(b0), "r"(b1));
}
// split float2 into packed bf16x2 hi + packed bf16x2 residual
__device__ __forceinline__ void split2(float vx, float vy, uint32_t& h, uint32_t& lo) {
    asm("cvt.rn.bf16x2.f32 %0, %1, %2;" : "=r"(h) : "f"(vy), "f"(vx));
    float rx = vx - __uint_as_float(h << 16);
    float ry = vy - __uint_as_float(h & 0xFFFF0000u);
    asm("cvt.rn.bf16x2.f32 %0, %1, %2;" : "=r"(lo) : "f"(ry), "f"(rx));
}
// Cody-Waite reduction (k <= 652 exact) + MUFU sincos
__device__ __forceinline__ void rope_sincos(float a, float& s, float& c) {
    float k = rintf(a * 0.15915494309189535f);
    float rr = fmaf(-k, 6.28125f, a);
    rr = fmaf(-k, 1.9353071795e-3f, rr);
    rr = fmaf(-k, 8.908910206762e-10f, rr);
    __sincosf(rr, &s, &c);
}

// SMEM: Bh [0,8K), Bl [8K,16K)
#define OFF_BH 0
#define OFF_BL 8192
#define SMEM_TOTAL 16384

// ---------------------------------------------------------------------------
// Main kernel: out = RoPE_diag( x @ M ) via bf16 mma.sync with hi/lo split.
// Warp = 32 rows = 2 m16 strips sharing every B fragment load.
// A fragments loaded straight from global as one float4 per (row, kc): the
// frag-order k permutation (folded into B at setup) makes v.xy = a0 pair and
// v.zw = a2 pair with no repacking. cos/sin computed in-register (MUFU).
// ---------------------------------------------------------------------------
__global__ __launch_bounds__(256, 2)
void rot_mma_kernel(const float* __restrict__ x, float* __restrict__ out,
                    const float* __restrict__ inv_freq) {
    extern __shared__ __align__(1024) char smem[];
    uint32_t sb = smem_u32(smem);
    int tid = threadIdx.x, w = tid >> 5, l = tid & 31;

    // stage B hi/lo swizzled ([n][frag-k] bf16, 128B rows, SW128)
    #pragma unroll
    for (int i = 0; i < 8; i++) {
        int e = tid + i * 256;
        int n = e >> 5, k2 = e & 31;
        unsigned sw = SW128(n * 128 + k2 * 4);
        unsigned bh = g_Bhi[e], bl = g_Blo[e];
        asm volatile("st.shared.b32 [%0], %1;" :: "r"(sb + OFF_BH + sw), "r"(bh) : "memory");
        asm volatile("st.shared.b32 [%0], %1;" :: "r"(sb + OFF_BL + sw), "r"(bl) : "memory");
    }
    __syncthreads();

    int g = l >> 2, c = l & 3;
    unsigned bRow0 = (unsigned)(l & 7) + ((unsigned)((l >> 4) & 1)) * 8u;
    unsigned bKoff = ((unsigned)((l >> 3) & 1)) * 16u;
    int cb = 2 * c;

    // per-lane RoPE frequencies: d = 8t+cb, 8t+cb+1
    float2 invf[4];
    #pragma unroll
    for (int t = 0; t < 4; t++)
        invf[t] = __ldg((const float2*)(inv_freq + 8 * t + cb));

    size_t rb0 = ((size_t)blockIdx.x * 8 + w) * 32;    // strip0; strip1 = +16
    const float* xb = x + rb0 * HDIM;

    float acc0[32], acc1[32];
    #pragma unroll
    for (int p = 0; p < 32; p++) { acc0[p] = 0.0f; acc1[p] = 0.0f; }

    #pragma unroll
    for (int kc = 0; kc < 4; kc++) {
        // A fragments for both strips, direct from global (phys k = kc*16+4c)
        uint32_t ah0[4], al0[4], ah1[4], al1[4];
        {
            const float4* p0 = (const float4*)(xb + g * HDIM + kc * 16 + 4 * c);
            float4 v0 = __ldg(p0);                       // row g
            float4 v1 = __ldg(p0 + 2 * HDIM / 4 * 4);    // row g+8 (8*HDIM floats)
            float4 u0 = __ldg(p0 + 4 * HDIM);            // row g+16 (16*HDIM floats /4)
            float4 u1 = __ldg(p0 + 6 * HDIM);            // row g+24
            split2(v0.x, v0.y, ah0[0], al0[0]);
            split2(v1.x, v1.y, ah0[1], al0[1]);
            split2(v0.z, v0.w, ah0[2], al0[2]);
            split2(v1.z, v1.w, ah0[3], al0[3]);
            split2(u0.x, u0.y, ah1[0], al1[0]);
            split2(u1.x, u1.y, ah1[1], al1[1]);
            split2(u0.z, u0.w, ah1[2], al1[2]);
            split2(u1.z, u1.w, ah1[3], al1[3]);
        }
        #pragma unroll
        for (int np = 0; np < 4; np++) {
            unsigned bad = SW128((16u * np + bRow0) * 128u + (unsigned)kc * 32u + bKoff);
            uint32_t bh[4];
            ldm_x4(bh, sb + OFF_BH + bad);
            mma16816(acc0 + (2 * np) * 4,     ah0, bh[0], bh[1]);
            mma16816(acc0 + (2 * np + 1) * 4, ah0, bh[2], bh[3]);
            mma16816(acc1 + (2 * np) * 4,     ah1, bh[0], bh[1]);
            mma16816(acc1 + (2 * np + 1) * 4, ah1, bh[2], bh[3]);
            mma16816(acc0 + (2 * np) * 4,     al0, bh[0], bh[1]);
            mma16816(acc0 + (2 * np + 1) * 4, al0, bh[2], bh[3]);
            mma16816(acc1 + (2 * np) * 4,     al1, bh[0], bh[1]);
            mma16816(acc1 + (2 * np + 1) * 4, al1, bh[2], bh[3]);
            uint32_t bl[4];
            ldm_x4(bl, sb + OFF_BL + bad);
            mma16816(acc0 + (2 * np) * 4,     ah0, bl[0], bl[1]);
            mma16816(acc0 + (2 * np + 1) * 4, ah0, bl[2], bl[3]);
            mma16816(acc1 + (2 * np) * 4,     ah1, bl[0], bl[1]);
            mma16816(acc1 + (2 * np + 1) * 4, ah1, bl[2], bl[3]);
        }
    }

    // RoPE epilogue per strip. D frag: lane -> rows {g, g+8}, cols
    // {8t+cb, 8t+cb+1}; n-tile t (y, cols<32) pairs with t+4 (z, cols+32).
    #pragma unroll
    for (int s = 0; s < 2; s++) {
        const float* acc = s ? acc1 : acc0;
        size_t rb = rb0 + (size_t)s * 16;
        float posf = (float)(int)((rb >> 4) & (SEQ - 1));
        float* o0 = out + (rb + g) * HDIM;
        float* o1 = out + (rb + g + 8) * HDIM;
        #pragma unroll
        for (int t = 0; t < 4; t++) {
            int cc2 = 8 * t + cb;
            float2 cc, ss;
            rope_sincos(posf * invf[t].x, ss.x, cc.x);
            rope_sincos(posf * invf[t].y, ss.y, cc.y);
            const float* y = acc + t * 4;
            const float* z = acc + (t + 4) * 4;
            float2 lo0, hi0, lo1, hi1;
            lo0.x = y[0] * cc.x - z[0] * ss.x;
            lo0.y = y[1] * cc.y - z[1] * ss.y;
            hi0.x = y[0] * ss.x + z[0] * cc.x;
            hi0.y = y[1] * ss.y + z[1] * cc.y;
            lo1.x = y[2] * cc.x - z[2] * ss.x;
            lo1.y = y[3] * cc.y - z[3] * ss.y;
            hi1.x = y[2] * ss.x + z[2] * cc.x;
            hi1.y = y[3] * ss.y + z[3] * cc.y;
            *(float2*)(o0 + cc2)      = lo0;
            *(float2*)(o0 + 32 + cc2) = hi0;
            *(float2*)(o1 + cc2)      = lo1;
            *(float2*)(o1 + 32 + cc2) = hi1;
        }
    }
}

// ---------------------------------------------------------------------------
extern "C" void kernel_launch(void* const* d_in, const int* in_sizes, int n_in,
                              void* d_out, int out_size) {
    const float* x           = (const float*)d_in[0];
    const float* thetas      = (const float*)d_in[1];
    const float* theta_scale = (const float*)d_in[2];
    const float* r_matrix    = (const float*)d_in[3];
    const float* inv_freq    = (const float*)d_in[4];
    const int*   pairs       = (const int*)d_in[5];
    float* out = (float*)d_out;

    setup_kernel<<<1, 256>>>(thetas, theta_scale, r_matrix, pairs);
    rot_mma_kernel<<<NBLOCKS, 256, SMEM_TOTAL>>>(x, out, inv_freq);
}

// round 9
// speedup vs baseline: 2.8219x; 1.0231x over previous
#include <cuda_runtime.h>
#include <cuda_bf16.h>
#include <math.h>
#include <cstdint>

#define HDIM   64
#define NROT   32
#define SEQ    4096
#define NROWS  (8 * 4096 * 16)       // 524288 rows of 64 floats
#define WARPS_PER_BLK 6
#define ROWS_PER_WARP 48             // 3 m16 strips sharing B fragments
#define ROWS_PER_BLK  (WARPS_PER_BLK * ROWS_PER_WARP)   // 288
#define NBLOCKS ((NROWS + ROWS_PER_BLK - 1) / ROWS_PER_BLK)  // 1821

// B = M^T split into bf16 hi/lo, packed bf16x2, k stored in FRAG order:
// frag pair fp within each 8-pair chunk holds phys pair 2*(fp&3)+(fp>>2).
__device__ unsigned g_Bhi[HDIM * 32];
__device__ unsigned g_Blo[HDIM * 32];

#define SW128(o) ((unsigned)(o) ^ ((((unsigned)(o)) >> 3) & 0x70u))

// ---------------------------------------------------------------------------
// Setup, 8 blocks: each block redundantly runs the 32-step blend on I (cheap),
// then computes an 8-column slice of M = Blend(I) @ R (RoPE col permutation
// folded) and that slice's transposed bf16 hi/lo frag-order split.
// ---------------------------------------------------------------------------
__global__ void setup_kernel(const float* __restrict__ thetas,
                             const float* __restrict__ theta_scale,
                             const float* __restrict__ r_matrix,
                             const int*   __restrict__ pairs) {
    __shared__ float E[HDIM * HDIM];
    __shared__ float sR[HDIM * HDIM];
    __shared__ float M2[HDIM * 8];       // this block's M column slice [k][dloc]
    int t = threadIdx.x;                 // 256 threads
    int b = blockIdx.x;                  // 8 blocks

    #pragma unroll
    for (int i = 0; i < 16; i++) sR[t + 256 * i] = r_matrix[t + 256 * i];

    if (t < HDIM) {
        int r = t;
        float row[HDIM];
        #pragma unroll
        for (int c = 0; c < HDIM; c++) row[c] = (r == c) ? 1.0f : 0.0f;
        float ts = theta_scale[0];
        for (int st = 0; st < NROT; st++) {
            int i = pairs[2 * st + 0];
            int j = pairs[2 * st + 1];
            float th = thetas[st] * ts;
            float c = cosf(th);
            float s = sinf(th);
            float xi = row[i];
            float xj = row[j];
            float gi = xi * c + xj * s;
            float gj = -xi * s + xj * c;
            row[i] = (2.0f * gi + xi - 2.0f * gi * c) * (1.0f / 3.0f);
            row[j] = (2.0f * gj + xj - 2.0f * gi * s) * (1.0f / 3.0f);
        }
        #pragma unroll
        for (int c = 0; c < HDIM; c++) E[r * HDIM + c] = row[c];
    }
    __syncthreads();

    // M slice: d = 8b + dloc, thread t -> r = t&63, dloc = t>>6 and (t>>6)+4
    {
        int r   = t & 63;
        int dl2 = t >> 6;
        #pragma unroll
        for (int q = 0; q < 2; q++) {
            int dloc = dl2 + 4 * q;
            int d = 8 * b + dloc;
            int col = (d < 32) ? (2 * d) : (2 * (d - 32) + 1);
            float acc = 0.0f;
            #pragma unroll
            for (int c = 0; c < HDIM; c++)
                acc = fmaf(E[r * HDIM + c], sR[c * HDIM + col], acc);
            M2[r * 8 + dloc] = acc;
        }
    }
    __syncthreads();

    // split slice: e = 256b + t; n = 8b + nloc
    {
        int e = 256 * b + t;
        int nloc = t >> 5;
        int fk2  = t & 31;
        int fp = fk2 & 7, chunk = fk2 >> 3;
        int p2 = chunk * 8 + 2 * (fp & 3) + (fp >> 2);   // phys pair
        float m0 = M2[(2 * p2)     * 8 + nloc];
        float m1 = M2[(2 * p2 + 1) * 8 + nloc];
        __nv_bfloat16 h0 = __float2bfloat16_rn(m0);
        __nv_bfloat16 h1 = __float2bfloat16_rn(m1);
        float r0 = m0 - __bfloat162float(h0);
        float r1 = m1 - __bfloat162float(h1);
        __nv_bfloat16 l0 = __float2bfloat16_rn(r0);
        __nv_bfloat16 l1 = __float2bfloat16_rn(r1);
        g_Bhi[e] = (unsigned)__bfloat16_as_ushort(h0) |
                   ((unsigned)__bfloat16_as_ushort(h1) << 16);
        g_Blo[e] = (unsigned)__bfloat16_as_ushort(l0) |
                   ((unsigned)__bfloat16_as_ushort(l1) << 16);
    }
}

// ---------------------------------------------------------------------------
// helpers
// ---------------------------------------------------------------------------
__device__ __forceinline__ uint32_t smem_u32(const void* p) {
    uint32_t a;
    asm("{ .reg .u64 t; cvta.to.shared.u64 t, %1; cvt.u32.u64 %0, t; }"
        : "=r"(a) : "l"(p));
    return a;
}
__device__ __forceinline__ void ldm_x4(uint32_t* r, uint32_t addr) {
    asm volatile("ldmatrix.sync.aligned.m8n8.x4.shared.b16 {%0,%1,%2,%3}, [%4];"
                 : "=r"(r[0]), "=r"(r[1]), "=r"(r[2]), "=r"(r[3]) : "r"(addr));
}
__device__ __forceinline__ void mma16816(float* c, const uint32_t* a,
                                         uint32_t b0, uint32_t b1) {
    asm volatile(
        "mma.sync.aligned.m16n8k16.row.col.f32.bf16.bf16.f32 "
        "{%0,%1,%2,%3}, {%4,%5,%6,%7}, {%8,%9}, {%0,%1,%2,%3};"
        : "+f"(c[0]), "+f"(c[1]), "+f"(c[2]), "+f"(c[3])
        : "r"(a[0]), "r"(a[1]), "r"(a[2]), "r"(a[3]), "r"(b0), "r"(b1));
}
// split float2 into packed bf16x2 hi + packed bf16x2 residual
__device__ __forceinline__ void split2(float vx, float vy, uint32_t& h, uint32_t& lo) {
    asm("cvt.rn.bf16x2.f32 %0, %1, %2;" : "=r"(h) : "f"(vy), "f"(vx));
    float rx = vx - __uint_as_float(h << 16);
    float ry = vy - __uint_as_float(h & 0xFFFF0000u);
    asm("cvt.rn.bf16x2.f32 %0, %1, %2;" : "=r"(lo) : "f"(ry), "f"(rx));
}
// Cody-Waite reduction (k <= 652 exact) + MUFU sincos
__device__ __forceinline__ void rope_sincos(float a, float& s, float& c) {
    float k = rintf(a * 0.15915494309189535f);
    float rr = fmaf(-k, 6.28125f, a);
    rr = fmaf(-k, 1.9353071795e-3f, rr);
    rr = fmaf(-k, 8.908910206762e-10f, rr);
    __sincosf(rr, &s, &c);
}

// SMEM: Bh [0,8K), Bl [8K,16K)
#define OFF_BH 0
#define OFF_BL 8192
#define SMEM_TOTAL 16384

// ---------------------------------------------------------------------------
// Main kernel: out = RoPE_diag( x @ M ) via bf16 mma.sync with hi/lo split.
// Warp = 48 rows = 3 m16 strips sharing every B fragment load (B smem bytes
// amortized over 1.5x more rows than R8). A fragments loaded straight from
// global as one float4 per (row, kc) thanks to the frag-order k permutation
// folded into B at setup. cos/sin computed in-register (MUFU).
// ---------------------------------------------------------------------------
__global__ __launch_bounds__(192, 2)
void rot_mma_kernel(const float* __restrict__ x, float* __restrict__ out,
                    const float* __restrict__ inv_freq) {
    extern __shared__ __align__(1024) char smem[];
    uint32_t sb = smem_u32(smem);
    int tid = threadIdx.x, w = tid >> 5, l = tid & 31;

    // stage B hi/lo swizzled ([n][frag-k] bf16, 128B rows, SW128), uint4 path
    {
        const uint4* bh4 = (const uint4*)g_Bhi;
        const uint4* bl4 = (const uint4*)g_Blo;
        for (int i = tid; i < 512; i += 192) {
            int n = i >> 3, kq = i & 7;          // kq = 16B unit within row
            unsigned sw = SW128(n * 128 + kq * 16);
            uint4 vh = bh4[i], vl = bl4[i];
            asm volatile("st.shared.v4.b32 [%0], {%1, %2, %3, %4};"
                         :: "r"(sb + OFF_BH + sw), "r"(vh.x), "r"(vh.y), "r"(vh.z), "r"(vh.w) : "memory");
            asm volatile("st.shared.v4.b32 [%0], {%1, %2, %3, %4};"
                         :: "r"(sb + OFF_BL + sw), "r"(vl.x), "r"(vl.y), "r"(vl.z), "r"(vl.w) : "memory");
        }
    }
    __syncthreads();

    int g = l >> 2, c = l & 3;
    unsigned bRow0 = (unsigned)(l & 7) + ((unsigned)((l >> 4) & 1)) * 8u;
    unsigned bKoff = ((unsigned)((l >> 3) & 1)) * 16u;
    int cb = 2 * c;

    // per-lane RoPE frequencies: d = 8t+cb, 8t+cb+1
    float2 invf[4];
    #pragma unroll
    for (int t = 0; t < 4; t++)
        invf[t] = __ldg((const float2*)(inv_freq + 8 * t + cb));

    size_t rb0 = ((size_t)blockIdx.x * WARPS_PER_BLK + w) * ROWS_PER_WARP;
    bool val[3];
    const float4* base[3];
    #pragma unroll
    for (int s = 0; s < 3; s++) {
        size_t rs = rb0 + 16 * s;
        val[s] = (rs + 16 <= (size_t)NROWS);
        base[s] = (const float4*)(x + (val[s] ? rs : 0) * HDIM);
    }

    float acc[3][32];
    #pragma unroll
    for (int s = 0; s < 3; s++)
        #pragma unroll
        for (int p = 0; p < 32; p++) acc[s][p] = 0.0f;

    #pragma unroll
    for (int kc = 0; kc < 4; kc++) {
        // A fragments for all 3 strips, direct from global (phys k = kc*16+4c)
        uint32_t ah[3][4], al[3][4];
        #pragma unroll
        for (int s = 0; s < 3; s++) {
            const float4* p = base[s] + g * 16 + kc * 4 + c;
            float4 v0 = __ldg(p);          // row g
            float4 v1 = __ldg(p + 128);    // row g+8
            split2(v0.x, v0.y, ah[s][0], al[s][0]);
            split2(v1.x, v1.y, ah[s][1], al[s][1]);
            split2(v0.z, v0.w, ah[s][2], al[s][2]);
            split2(v1.z, v1.w, ah[s][3], al[s][3]);
        }
        #pragma unroll
        for (int np = 0; np < 4; np++) {
            unsigned bad = SW128((16u * np + bRow0) * 128u + (unsigned)kc * 32u + bKoff);
            uint32_t bh[4];
            ldm_x4(bh, sb + OFF_BH + bad);
            #pragma unroll
            for (int s = 0; s < 3; s++) {
                mma16816(acc[s] + (2 * np) * 4,     ah[s], bh[0], bh[1]);
                mma16816(acc[s] + (2 * np + 1) * 4, ah[s], bh[2], bh[3]);
            }
            #pragma unroll
            for (int s = 0; s < 3; s++) {
                mma16816(acc[s] + (2 * np) * 4,     al[s], bh[0], bh[1]);
                mma16816(acc[s] + (2 * np + 1) * 4, al[s], bh[2], bh[3]);
            }
            uint32_t bl[4];
            ldm_x4(bl, sb + OFF_BL + bad);
            #pragma unroll
            for (int s = 0; s < 3; s++) {
                mma16816(acc[s] + (2 * np) * 4,     ah[s], bl[0], bl[1]);
                mma16816(acc[s] + (2 * np + 1) * 4, ah[s], bl[2], bl[3]);
            }
        }
    }

    // RoPE epilogue per strip. D frag: lane -> rows {g, g+8}, cols
    // {8t+cb, 8t+cb+1}; n-tile t (y, cols<32) pairs with t+4 (z, cols+32).
    #pragma unroll
    for (int s = 0; s < 3; s++) {
        if (!val[s]) continue;
        size_t rb = rb0 + 16 * s;
        float posf = (float)(int)((rb >> 4) & (SEQ - 1));
        float* o0 = out + (rb + g) * HDIM;
        float* o1 = out + (rb + g + 8) * HDIM;
        #pragma unroll
        for (int t = 0; t < 4; t++) {
            int cc2 = 8 * t + cb;
            float2 cc, ss;
            rope_sincos(posf * invf[t].x, ss.x, cc.x);
            rope_sincos(posf * invf[t].y, ss.y, cc.y);
            const float* y = acc[s] + t * 4;
            const float* z = acc[s] + (t + 4) * 4;
            float2 lo0, hi0, lo1, hi1;
            lo0.x = y[0] * cc.x - z[0] * ss.x;
            lo0.y = y[1] * cc.y - z[1] * ss.y;
            hi0.x = y[0] * ss.x + z[0] * cc.x;
            hi0.y = y[1] * ss.y + z[1] * cc.y;
            lo1.x = y[2] * cc.x - z[2] * ss.x;
            lo1.y = y[3] * cc.y - z[3] * ss.y;
            hi1.x = y[2] * ss.x + z[2] * cc.x;
            hi1.y = y[3] * ss.y + z[3] * cc.y;
            *(float2*)(o0 + cc2)      = lo0;
            *(float2*)(o0 + 32 + cc2) = hi0;
            *(float2*)(o1 + cc2)      = lo1;
            *(float2*)(o1 + 32 + cc2) = hi1;
        }
    }
}

// ---------------------------------------------------------------------------
extern "C" void kernel_launch(void* const* d_in, const int* in_sizes, int n_in,
                              void* d_out, int out_size) {
    const float* x           = (const float*)d_in[0];
    const float* thetas      = (const float*)d_in[1];
    const float* theta_scale = (const float*)d_in[2];
    const float* r_matrix    = (const float*)d_in[3];
    const float* inv_freq    = (const float*)d_in[4];
    const int*   pairs       = (const int*)d_in[5];
    float* out = (float*)d_out;

    setup_kernel<<<8, 256>>>(thetas, theta_scale, r_matrix, pairs);
    rot_mma_kernel<<<NBLOCKS, 192, SMEM_TOTAL>>>(x, out, inv_freq);
}

// round 10
// speedup vs baseline: 2.9940x; 1.0610x over previous
#include <cuda_runtime.h>
#include <cuda_bf16.h>
#include <math.h>
#include <cstdint>

#define HDIM   64
#define NROT   32
#define SEQ    4096
#define NROWS  (8 * 4096 * 16)       // 524288 rows of 64 floats
#define NBLOCKS (NROWS / (8 * 32))   // 2048: 8 warps x 32 rows

// B = M^T split into bf16 hi/lo, packed bf16x2, k stored in FRAG order:
// frag pair fp within each 8-pair chunk holds phys pair 2*(fp&3)+(fp>>2).
__device__ unsigned g_Bhi[HDIM * 32];
__device__ unsigned g_Blo[HDIM * 32];

#define SW128(o) ((unsigned)(o) ^ ((((unsigned)(o)) >> 3) & 0x70u))

// ---------------------------------------------------------------------------
// Setup, 8 blocks (R9, verified): each block redundantly runs the 32-step
// blend on I, then computes an 8-column slice of M = Blend(I) @ R (RoPE col
// permutation folded) and that slice's transposed bf16 hi/lo frag-order split.
// ---------------------------------------------------------------------------
__global__ void setup_kernel(const float* __restrict__ thetas,
                             const float* __restrict__ theta_scale,
                             const float* __restrict__ r_matrix,
                             const int*   __restrict__ pairs) {
    __shared__ float E[HDIM * HDIM];
    __shared__ float sR[HDIM * HDIM];
    __shared__ float M2[HDIM * 8];       // this block's M column slice [k][dloc]
    int t = threadIdx.x;                 // 256 threads
    int b = blockIdx.x;                  // 8 blocks

    #pragma unroll
    for (int i = 0; i < 16; i++) sR[t + 256 * i] = r_matrix[t + 256 * i];

    if (t < HDIM) {
        int r = t;
        float row[HDIM];
        #pragma unroll
        for (int c = 0; c < HDIM; c++) row[c] = (r == c) ? 1.0f : 0.0f;
        float ts = theta_scale[0];
        for (int st = 0; st < NROT; st++) {
            int i = pairs[2 * st + 0];
            int j = pairs[2 * st + 1];
            float th = thetas[st] * ts;
            float c = cosf(th);
            float s = sinf(th);
            float xi = row[i];
            float xj = row[j];
            float gi = xi * c + xj * s;
            float gj = -xi * s + xj * c;
            row[i] = (2.0f * gi + xi - 2.0f * gi * c) * (1.0f / 3.0f);
            row[j] = (2.0f * gj + xj - 2.0f * gi * s) * (1.0f / 3.0f);
        }
        #pragma unroll
        for (int c = 0; c < HDIM; c++) E[r * HDIM + c] = row[c];
    }
    __syncthreads();

    {   // M slice: d = 8b + dloc
        int r   = t & 63;
        int dl2 = t >> 6;
        #pragma unroll
        for (int q = 0; q < 2; q++) {
            int dloc = dl2 + 4 * q;
            int d = 8 * b + dloc;
            int col = (d < 32) ? (2 * d) : (2 * (d - 32) + 1);
            float acc = 0.0f;
            #pragma unroll
            for (int c = 0; c < HDIM; c++)
                acc = fmaf(E[r * HDIM + c], sR[c * HDIM + col], acc);
            M2[r * 8 + dloc] = acc;
        }
    }
    __syncthreads();

    {   // split slice: e = 256b + t; n = 8b + nloc
        int e = 256 * b + t;
        int nloc = t >> 5;
        int fk2  = t & 31;
        int fp = fk2 & 7, chunk = fk2 >> 3;
        int p2 = chunk * 8 + 2 * (fp & 3) + (fp >> 2);   // phys pair
        float m0 = M2[(2 * p2)     * 8 + nloc];
        float m1 = M2[(2 * p2 + 1) * 8 + nloc];
        __nv_bfloat16 h0 = __float2bfloat16_rn(m0);
        __nv_bfloat16 h1 = __float2bfloat16_rn(m1);
        float r0 = m0 - __bfloat162float(h0);
        float r1 = m1 - __bfloat162float(h1);
        __nv_bfloat16 l0 = __float2bfloat16_rn(r0);
        __nv_bfloat16 l1 = __float2bfloat16_rn(r1);
        g_Bhi[e] = (unsigned)__bfloat16_as_ushort(h0) |
                   ((unsigned)__bfloat16_as_ushort(h1) << 16);
        g_Blo[e] = (unsigned)__bfloat16_as_ushort(l0) |
                   ((unsigned)__bfloat16_as_ushort(l1) << 16);
    }
}

// ---------------------------------------------------------------------------
// helpers
// ---------------------------------------------------------------------------
__device__ __forceinline__ uint32_t smem_u32(const void* p) {
    uint32_t a;
    asm("{ .reg .u64 t; cvta.to.shared.u64 t, %1; cvt.u32.u64 %0, t; }"
        : "=r"(a) : "l"(p));
    return a;
}
__device__ __forceinline__ void ldm_x4(uint32_t* r, uint32_t addr) {
    asm volatile("ldmatrix.sync.aligned.m8n8.x4.shared.b16 {%0,%1,%2,%3}, [%4];"
                 : "=r"(r[0]), "=r"(r[1]), "=r"(r[2]), "=r"(r[3]) : "r"(addr));
}
__device__ __forceinline__ void mma16816(float* c, const uint32_t* a,
                                         uint32_t b0, uint32_t b1) {
    asm volatile(
        "mma.sync.aligned.m16n8k16.row.col.f32.bf16.bf16.f32 "
        "{%0,%1,%2,%3}, {%4,%5,%6,%7}, {%8,%9}, {%0,%1,%2,%3};"
        : "+f"(c[0]), "+f"(c[1]), "+f"(c[2]), "+f"(c[3])
        : "r"(a[0]), "r"(a[1]), "r"(a[2]), "r"(a[3]), "r"(b0), "r"(b1));
}
// split float2 into packed bf16x2 hi + packed bf16x2 residual
__device__ __forceinline__ void split2(float vx, float vy, uint32_t& h, uint32_t& lo) {
    asm("cvt.rn.bf16x2.f32 %0, %1, %2;" : "=r"(h) : "f"(vy), "f"(vx));
    float rx = vx - __uint_as_float(h << 16);
    float ry = vy - __uint_as_float(h & 0xFFFF0000u);
    asm("cvt.rn.bf16x2.f32 %0, %1, %2;" : "=r"(lo) : "f"(ry), "f"(rx));
}
// Cody-Waite reduction (k <= 652 exact) + MUFU sincos
__device__ __forceinline__ void rope_sincos(float a, float& s, float& c) {
    float k = rintf(a * 0.15915494309189535f);
    float rr = fmaf(-k, 6.28125f, a);
    rr = fmaf(-k, 1.9353071795e-3f, rr);
    rr = fmaf(-k, 8.908910206762e-10f, rr);
    __sincosf(rr, &s, &c);
}

// SMEM: Bh [0,8K), Bl [8K,16K)
#define OFF_BH 0
#define OFF_BL 8192
#define SMEM_TOTAL 16384

// ---------------------------------------------------------------------------
// Main kernel: out = RoPE_diag( x @ M ) via bf16 mma.sync with hi/lo split.
// Warp = 32 rows = 2 m16 strips. Latency-optimized structure:
//   1) all 16 A LDG.128 issue back-to-back (MLP=16/warp),
//   2) B smem staging overlaps the A latency,
//   3) one convert pass -> 64 persistent frag regs,
//   4) n-dim processed in 2 time-halves (np = h and h+2) so acc = 32 regs;
//      RoPE pair (d, d+32) = tiles (2h+j, 2h+4+j) stays within a half.
// Traffic identical to R8; only the latency structure changes.
// ---------------------------------------------------------------------------
__global__ __launch_bounds__(256, 2)
void rot_mma_kernel(const float* __restrict__ x, float* __restrict__ out,
                    const float* __restrict__ inv_freq) {
    extern __shared__ __align__(1024) char smem[];
    uint32_t sb = smem_u32(smem);
    int tid = threadIdx.x, w = tid >> 5, l = tid & 31;
    int g = l >> 2, c = l & 3;
    int cb = 2 * c;

    // ---- 1) front-batched A loads: 16 independent LDG.128 ----
    size_t rb0 = ((size_t)blockIdx.x * 8 + w) * 32;    // strip0; strip1 = +16
    const float4* b4 = (const float4*)(x + rb0 * HDIM) + g * 16 + c;
    float4 v[4][4];   // [row-group g+8*rg][kc]
    #pragma unroll
    for (int rg = 0; rg < 4; rg++)
        #pragma unroll
        for (int kc = 0; kc < 4; kc++)
            v[rg][kc] = __ldg(b4 + rg * 128 + kc * 4);

    // ---- 2) stage B hi/lo swizzled (overlaps A load latency) ----
    {
        const uint4* bh4 = (const uint4*)g_Bhi;
        const uint4* bl4 = (const uint4*)g_Blo;
        #pragma unroll
        for (int rep = 0; rep < 2; rep++) {
            int i = tid + rep * 256;
            int n = i >> 3, kq = i & 7;
            unsigned sw = SW128(n * 128 + kq * 16);
            uint4 vh = bh4[i], vl = bl4[i];
            asm volatile("st.shared.v4.b32 [%0], {%1, %2, %3, %4};"
                         :: "r"(sb + OFF_BH + sw), "r"(vh.x), "r"(vh.y), "r"(vh.z), "r"(vh.w) : "memory");
            asm volatile("st.shared.v4.b32 [%0], {%1, %2, %3, %4};"
                         :: "r"(sb + OFF_BL + sw), "r"(vl.x), "r"(vl.y), "r"(vl.z), "r"(vl.w) : "memory");
        }
    }
    __syncthreads();

    // ---- 3) convert to persistent A fragments (64 regs) ----
    uint32_t ah[2][4][4], al[2][4][4];   // [strip][kc][frag]
    #pragma unroll
    for (int s = 0; s < 2; s++)
        #pragma unroll
        for (int kc = 0; kc < 4; kc++) {
            float4 r0 = v[2 * s][kc];      // row g
            float4 r1 = v[2 * s + 1][kc];  // row g+8
            split2(r0.x, r0.y, ah[s][kc][0], al[s][kc][0]);
            split2(r1.x, r1.y, ah[s][kc][1], al[s][kc][1]);
            split2(r0.z, r0.w, ah[s][kc][2], al[s][kc][2]);
            split2(r1.z, r1.w, ah[s][kc][3], al[s][kc][3]);
        }

    unsigned bRow0 = (unsigned)(l & 7) + ((unsigned)((l >> 4) & 1)) * 8u;
    unsigned bKoff = ((unsigned)((l >> 3) & 1)) * 16u;

    // ---- 4) two n-halves ----
    #pragma unroll
    for (int h = 0; h < 2; h++) {
        float acc[2][16];
        #pragma unroll
        for (int s = 0; s < 2; s++)
            #pragma unroll
            for (int p = 0; p < 16; p++) acc[s][p] = 0.0f;

        #pragma unroll
        for (int kc = 0; kc < 4; kc++)
            #pragma unroll
            for (int j = 0; j < 2; j++) {        // j=0: y (np=h), j=1: z (np=h+2)
                int np = h + 2 * j;
                unsigned bad = SW128((16u * np + bRow0) * 128u + (unsigned)kc * 32u + bKoff);
                uint32_t bh[4], bl[4];
                ldm_x4(bh, sb + OFF_BH + bad);
                ldm_x4(bl, sb + OFF_BL + bad);
                #pragma unroll
                for (int s = 0; s < 2; s++) {
                    float* a0 = acc[s] + 8 * j;
                    float* a1 = acc[s] + 8 * j + 4;
                    mma16816(a0, ah[s][kc], bh[0], bh[1]);
                    mma16816(a1, ah[s][kc], bh[2], bh[3]);
                    mma16816(a0, al[s][kc], bh[0], bh[1]);
                    mma16816(a1, al[s][kc], bh[2], bh[3]);
                    mma16816(a0, ah[s][kc], bl[0], bl[1]);
                    mma16816(a1, ah[s][kc], bl[2], bl[3]);
                }
            }

        // epilogue for this half: y tile (2h+j2) pairs z tile (2h+4+j2);
        // d0 = 16h + 8*j2 + cb
        #pragma unroll
        for (int s = 0; s < 2; s++) {
            size_t rb = rb0 + 16 * s;
            float posf = (float)(int)((rb >> 4) & (SEQ - 1));
            float* o0 = out + (rb + g) * HDIM;
            float* o1 = out + (rb + g + 8) * HDIM;
            #pragma unroll
            for (int j2 = 0; j2 < 2; j2++) {
                int d0 = 16 * h + 8 * j2 + cb;
                float2 fr = __ldg((const float2*)(inv_freq + d0));
                float2 cc, ss;
                rope_sincos(posf * fr.x, ss.x, cc.x);
                rope_sincos(posf * fr.y, ss.y, cc.y);
                const float* y = acc[s] + 4 * j2;
                const float* z = acc[s] + 8 + 4 * j2;
                float2 lo0, hi0, lo1, hi1;
                lo0.x = y[0] * cc.x - z[0] * ss.x;
                lo0.y = y[1] * cc.y - z[1] * ss.y;
                hi0.x = y[0] * ss.x + z[0] * cc.x;
                hi0.y = y[1] * ss.y + z[1] * cc.y;
                lo1.x = y[2] * cc.x - z[2] * ss.x;
                lo1.y = y[3] * cc.y - z[3] * ss.y;
                hi1.x = y[2] * ss.x + z[2] * cc.x;
                hi1.y = y[3] * ss.y + z[3] * cc.y;
                *(float2*)(o0 + d0)      = lo0;
                *(float2*)(o0 + 32 + d0) = hi0;
                *(float2*)(o1 + d0)      = lo1;
                *(float2*)(o1 + 32 + d0) = hi1;
            }
        }
    }
}

// ---------------------------------------------------------------------------
extern "C" void kernel_launch(void* const* d_in, const int* in_sizes, int n_in,
                              void* d_out, int out_size) {
    const float* x           = (const float*)d_in[0];
    const float* thetas      = (const float*)d_in[1];
    const float* theta_scale = (const float*)d_in[2];
    const float* r_matrix    = (const float*)d_in[3];
    const float* inv_freq    = (const float*)d_in[4];
    const int*   pairs       = (const int*)d_in[5];
    float* out = (float*)d_out;

    setup_kernel<<<8, 256>>>(thetas, theta_scale, r_matrix, pairs);
    rot_mma_kernel<<<NBLOCKS, 256, SMEM_TOTAL>>>(x, out, inv_freq);
}